// round 9
// baseline (speedup 1.0000x reference)
#include <cuda_runtime.h>
#include <cuda_bf16.h>
#include <cstdint>

// ---------------- Problem constants ----------------
#define NN 8192
#define DD 768
#define TILE 128
#define KC 64                // bf16 k-elems per smem stage (128B rows)
#define NKC (DD / KC)        // 12
#define NT (NN / TILE)       // 64
#define INV_T 10.0f
#define EPS_LOG 1e-6f
#define EPS_NORM 1e-8f

// ---------------- SMEM layout (bytes): 2 stages of (A 16K + B 16K) ----------------
#define OFF_A0 0
#define OFF_A1 16384
#define OFF_B0 32768
#define OFF_B1 49152
#define OFF_RACC 65536            // 6*128 floats
#define OFF_CACC (65536 + 3072)   // 6*128 floats
#define SMEM2 (65536 + 6144)      // 71680 B -> 3 CTAs/SM by smem

// ---------------- Global scratch ----------------
__device__ __nv_bfloat16 g_fn[(size_t)NN * DD];
__device__ float g_neg[NN], g_pos[NN], g_t1[NN], g_t2[NN], g_t3[NN], g_t4[NN];
__device__ float g_pr[NN];

// ---------------- Helpers ----------------
__device__ __forceinline__ uint32_t smem_u32(const void* p) {
    uint32_t a;
    asm("{ .reg .u64 t; cvta.to.shared.u64 t, %1; cvt.u32.u64 %0, t; }" : "=r"(a) : "l"(p));
    return a;
}
#define SWZ128(o) ((o) ^ (((o) >> 3) & 0x70))

__device__ __forceinline__ void cp16(uint32_t s, const void* g) {
    asm volatile("cp.async.cg.shared.global [%0], [%1], 16;"
                 :: "r"(s), "l"((uint64_t)__cvta_generic_to_global(g)));
}
#define CP_COMMIT() asm volatile("cp.async.commit_group;" ::: "memory")
#define CP_WAIT(n)  asm volatile("cp.async.wait_group %0;" :: "n"(n) : "memory")

__device__ __forceinline__ void l2_prefetch(const float* p) {
    asm volatile("prefetch.global.L2 [%0];" :: "l"((uint64_t)__cvta_generic_to_global(p)));
}

__device__ __forceinline__ void ldsm_x4(uint32_t* r, uint32_t addr) {
    asm volatile("ldmatrix.sync.aligned.m8n8.x4.shared.b16 {%0,%1,%2,%3}, [%4];"
                 : "=r"(r[0]), "=r"(r[1]), "=r"(r[2]), "=r"(r[3]) : "r"(addr));
}
__device__ __forceinline__ void mma16816(float* c, const uint32_t* a, uint32_t b0, uint32_t b1) {
    asm volatile("mma.sync.aligned.m16n8k16.row.col.f32.bf16.bf16.f32 "
                 "{%0,%1,%2,%3}, {%4,%5,%6,%7}, {%8,%9}, {%0,%1,%2,%3};"
                 : "+f"(c[0]), "+f"(c[1]), "+f"(c[2]), "+f"(c[3])
                 : "r"(a[0]), "r"(a[1]), "r"(a[2]), "r"(a[3]), "r"(b0), "r"(b1));
}

__device__ __forceinline__ float warp_sum(float v) {
    #pragma unroll
    for (int o = 16; o; o >>= 1) v += __shfl_xor_sync(0xFFFFFFFFu, v, o);
    return v;
}
__device__ __forceinline__ float block_sum(float v, float* red) {
    v = warp_sum(v);
    int w = threadIdx.x >> 5, l = threadIdx.x & 31;
    if (l == 0) red[w] = v;
    __syncthreads();
    int nw = blockDim.x >> 5;
    v = (threadIdx.x < (unsigned)nw) ? red[threadIdx.x] : 0.0f;
    if (w == 0) v = warp_sum(v);
    if (threadIdx.x == 0) red[0] = v;
    __syncthreads();
    return red[0];
}

// ---------------- K1: normalize -> bf16 (+ zero accumulators for this row) ----------------
__global__ __launch_bounds__(256) void k1_norm(const float* __restrict__ f) {
    __shared__ float red[32];
    int i = blockIdx.x;
    if (threadIdx.x == 0) {
        g_neg[i] = 0.f; g_pos[i] = 0.f; g_t1[i] = 0.f;
        g_t2[i] = 0.f; g_t3[i] = 0.f; g_t4[i] = 0.f;
    }
    const float* row = f + (size_t)i * DD;
    float v[3], ss = 0.0f;
    #pragma unroll
    for (int k = 0; k < 3; k++) { v[k] = row[threadIdx.x + k * 256]; ss += v[k] * v[k]; }
    float tot = block_sum(ss, red);
    float inv = 1.0f / fmaxf(sqrtf(tot), EPS_NORM);
    __nv_bfloat16* o = g_fn + (size_t)i * DD;
    #pragma unroll
    for (int k = 0; k < 3; k++) o[threadIdx.x + k * 256] = __float2bfloat16(v[k] * inv);
}

// ---------------- K2: mma.sync GEMM (upper triangle, 2D grid) + dual epilogue ----------------
__device__ __forceinline__ void load_tiles(uint32_t sA, uint32_t sB,
                                           const __nv_bfloat16* A0, const __nv_bfloat16* B0,
                                           int kc, int tid) {
    #pragma unroll
    for (int q = 0; q < 4; q++) {
        int idx = tid + q * 256;
        int r = idx >> 3, seg = idx & 7;              // 128 rows x 8 x 16B
        uint32_t so = SWZ128((uint32_t)(r * 128 + seg * 16));
        cp16(sA + so, A0 + (size_t)r * DD + kc * KC + seg * 8);
        cp16(sB + so, B0 + (size_t)r * DD + kc * KC + seg * 8);
    }
}

__global__ __launch_bounds__(256, 2) void k2_gemm(const float* __restrict__ pm,
                                                  const float* __restrict__ nm) {
    int it = blockIdx.y, jt = blockIdx.x;
    if (jt < it) return;                 // symmetric: upper triangle only
    bool diag = (it == jt);

    extern __shared__ char smem[];
    uint32_t sb = smem_u32(smem);
    int tid = threadIdx.x, l = tid & 31, wid = tid >> 5;
    int wm = wid & 3, wn = wid >> 2;     // 4x2 warp grid; warp tile 32x64

    int ibase = it * TILE, jbase = jt * TILE;

    // ---- L2 prefetch of all mask lines this CTA reads (overlaps GEMM mainloop) ----
    {
        int nlines = diag ? 1024 : 2048;
        for (int q = 0; q < 8; q++) {
            int idx = tid + q * 256;
            if (idx >= nlines) break;
            int sel = idx >> 10;             // 0: row-orient, 1: transposed
            int rem = idx & 1023;            // 128 rows x 4 lines x 2 masks
            int r = rem >> 3, line = (rem >> 1) & 3, m = rem & 1;
            size_t off = sel ? ((size_t)(jbase + r) * NN + ibase + line * 32)
                             : ((size_t)(ibase + r) * NN + jbase + line * 32);
            l2_prefetch((m ? nm : pm) + off);
        }
    }

    float* racc = (float*)(smem + OFF_RACC);
    float* cacc = (float*)(smem + OFF_CACC);
    for (int z = tid; z < 1536; z += 256) racc[z] = 0.f;   // racc+cacc contiguous

    const __nv_bfloat16* A0 = g_fn + (size_t)it * TILE * DD;
    const __nv_bfloat16* B0 = g_fn + (size_t)jt * TILE * DD;

    float acc[2][8][4];
    #pragma unroll
    for (int m = 0; m < 2; m++)
        #pragma unroll
        for (int n = 0; n < 8; n++)
            #pragma unroll
            for (int x = 0; x < 4; x++) acc[m][n][x] = 0.f;

    load_tiles(sb + OFF_A0, sb + OFF_B0, A0, B0, 0, tid);
    CP_COMMIT();

    uint32_t aRow = (uint32_t)((wm * 32 + (l & 15)) * 128);
    uint32_t aK   = (uint32_t)((l >> 4) * 16);
    uint32_t bRow = (uint32_t)((wn * 64 + (l & 7) + ((l >> 4) << 3)) * 128);
    uint32_t bK   = (uint32_t)(((l >> 3) & 1) * 16);

    for (int kc = 0; kc < NKC; kc++) {
        if (kc + 1 < NKC) {
            load_tiles(sb + ((kc + 1) & 1 ? OFF_A1 : OFF_A0),
                       sb + ((kc + 1) & 1 ? OFF_B1 : OFF_B0), A0, B0, kc + 1, tid);
            CP_COMMIT();
            CP_WAIT(1);
        } else {
            CP_WAIT(0);
        }
        __syncthreads();
        uint32_t sA = sb + ((kc & 1) ? OFF_A1 : OFF_A0);
        uint32_t sB = sb + ((kc & 1) ? OFF_B1 : OFF_B0);
        #pragma unroll
        for (int ks = 0; ks < 4; ks++) {
            uint32_t a[2][4], b[4][4];
            #pragma unroll
            for (int mf = 0; mf < 2; mf++)
                ldsm_x4(a[mf], sA + (SWZ128(aRow + (uint32_t)(mf * 16 * 128)) ^ (aK + ks * 32)));
            #pragma unroll
            for (int p2 = 0; p2 < 4; p2++)
                ldsm_x4(b[p2], sB + (SWZ128(bRow + (uint32_t)(p2 * 16 * 128)) ^ (bK + ks * 32)));
            #pragma unroll
            for (int mf = 0; mf < 2; mf++)
                #pragma unroll
                for (int nf = 0; nf < 8; nf++)
                    mma16816(acc[mf][nf], a[mf], b[nf >> 1][(nf & 1) * 2], b[nf >> 1][(nf & 1) * 2 + 1]);
        }
        __syncthreads();
    }

    // ---- epilogue: masks + exp; 6 moments, both orientations ----
    int qrow = l >> 2, qcol = (l & 3) * 2;
    float rl[4][6];
    #pragma unroll
    for (int i2 = 0; i2 < 4; i2++)
        #pragma unroll
        for (int v = 0; v < 6; v++) rl[i2][v] = 0.f;

    #pragma unroll
    for (int nf = 0; nf < 8; nf++) {
        float cl[2][6];
        #pragma unroll
        for (int e = 0; e < 2; e++)
            #pragma unroll
            for (int v = 0; v < 6; v++) cl[e][v] = 0.f;

        #pragma unroll
        for (int mf = 0; mf < 2; mf++) {
            #pragma unroll
            for (int h = 0; h < 2; h++) {
                int r = wm * 32 + mf * 16 + qrow + h * 8;
                int i = ibase + r;
                int cb = wn * 64 + nf * 8 + qcol;
                int j0 = jbase + cb;
                float2 pv = *(const float2*)(pm + (size_t)i * NN + j0);
                float2 nv = *(const float2*)(nm + (size_t)i * NN + j0);
                #pragma unroll
                for (int e = 0; e < 2; e++) {
                    float p = e ? pv.y : pv.x;
                    float n = e ? nv.y : nv.x;
                    int ccol = cb + e;
                    if (diag && r == ccol) { p = 0.f; n = 0.f; }
                    float s = acc[mf][nf][h * 2 + e];
                    float ep = __expf(INV_T * s);
                    float y = __fdividef(1.0f, ep);
                    float* R = rl[mf * 2 + h];
                    R[0] += n * ep; R[1] += p; R[2] += p * s;
                    float py = p * y; R[3] += py; py *= y; R[4] += py; py *= y; R[5] += py;
                    if (!diag) {
                        size_t gj = (size_t)(jbase + ccol) * NN + i;
                        float pT = pm[gj], nT = nm[gj];
                        float* C = cl[e];
                        C[0] += nT * ep; C[1] += pT; C[2] += pT * s;
                        float pTy = pT * y; C[3] += pTy; pTy *= y; C[4] += pTy; pTy *= y; C[5] += pTy;
                    }
                }
            }
        }
        if (!diag) {
            #pragma unroll
            for (int e = 0; e < 2; e++) {
                int ccol = wn * 64 + nf * 8 + qcol + e;
                #pragma unroll
                for (int v = 0; v < 6; v++) {
                    float val = cl[e][v];
                    val += __shfl_xor_sync(0xFFFFFFFFu, val, 4);
                    val += __shfl_xor_sync(0xFFFFFFFFu, val, 8);
                    val += __shfl_xor_sync(0xFFFFFFFFu, val, 16);
                    if (l < 4) atomicAdd(&cacc[v * 128 + ccol], val);
                }
            }
        }
    }
    #pragma unroll
    for (int i2 = 0; i2 < 4; i2++) {
        int r = wm * 32 + (i2 >> 1) * 16 + qrow + (i2 & 1) * 8;
        #pragma unroll
        for (int v = 0; v < 6; v++) {
            float val = rl[i2][v];
            val += __shfl_xor_sync(0xFFFFFFFFu, val, 1);
            val += __shfl_xor_sync(0xFFFFFFFFu, val, 2);
            if ((l & 3) == 0) atomicAdd(&racc[v * 128 + r], val);
        }
    }
    __syncthreads();
    if (tid < 128) {
        atomicAdd(&g_neg[ibase + tid], racc[tid]);
        atomicAdd(&g_pos[ibase + tid], racc[128 + tid]);
        atomicAdd(&g_t1[ibase + tid],  racc[256 + tid]);
        atomicAdd(&g_t2[ibase + tid],  racc[384 + tid]);
        atomicAdd(&g_t3[ibase + tid],  racc[512 + tid]);
        atomicAdd(&g_t4[ibase + tid],  racc[640 + tid]);
        if (!diag) {
            atomicAdd(&g_neg[jbase + tid], cacc[tid]);
            atomicAdd(&g_pos[jbase + tid], cacc[128 + tid]);
            atomicAdd(&g_t1[jbase + tid],  cacc[256 + tid]);
            atomicAdd(&g_t2[jbase + tid],  cacc[384 + tid]);
            atomicAdd(&g_t3[jbase + tid],  cacc[512 + tid]);
            atomicAdd(&g_t4[jbase + tid],  cacc[640 + tid]);
        }
    }
}

// ---------------- K4a: per-row loss ----------------
__global__ __launch_bounds__(256) void k4a_row() {
    int i = blockIdx.x * blockDim.x + threadIdx.x;
    if (i >= NN) return;
    float neg = g_neg[i], pos = g_pos[i];
    float c = EPS_LOG * neg;
    float corr = c * g_t2[i] - 0.5f * c * c * g_t3[i] + (c * c * c * (1.0f / 3.0f)) * g_t4[i];
    float num = pos * logf(neg) - INV_T * g_t1[i] - corr;
    g_pr[i] = num / (pos > 0.0f ? pos : 1.0f);
}

// ---------------- K4b: final mean ----------------
__global__ __launch_bounds__(1024) void k4b_final(float* __restrict__ out) {
    __shared__ float red[32];
    float sum = 0.0f;
    #pragma unroll
    for (int k = 0; k < NN / 1024; k++) sum += g_pr[threadIdx.x + k * 1024];
    float tot = block_sum(sum, red);
    if (threadIdx.x == 0) out[0] = tot / (float)NN;
}

// ---------------- launch ----------------
extern "C" void kernel_launch(void* const* d_in, const int* in_sizes, int n_in,
                              void* d_out, int out_size) {
    const float* features = (const float*)d_in[0];
    const float* pmask    = (const float*)d_in[1];
    const float* nmask    = (const float*)d_in[2];
    float* out = (float*)d_out;

    cudaFuncSetAttribute(k2_gemm, cudaFuncAttributeMaxDynamicSharedMemorySize, SMEM2);

    k1_norm<<<NN, 256>>>(features);
    dim3 grid(NT, NT);
    k2_gemm<<<grid, 256, SMEM2>>>(pmask, nmask);
    k4a_row<<<NN / 256, 256>>>();
    k4b_final<<<1, 1024>>>(out);
}

// round 10
// speedup vs baseline: 1.0212x; 1.0212x over previous
#include <cuda_runtime.h>
#include <cuda_bf16.h>
#include <cstdint>

// ---------------- Problem constants ----------------
#define NN 8192
#define DD 768
#define TILE 128
#define KC 64                // bf16 k-elems per smem stage (128B rows)
#define NKC (DD / KC)        // 12
#define NT (NN / TILE)       // 64
#define INV_T 10.0f
#define EPS_LOG 1e-6f
#define EPS_NORM 1e-8f

// ---------------- SMEM layout (bytes): 2 stages of (A 16K + B 16K) ----------------
#define OFF_A0 0
#define OFF_A1 16384
#define OFF_B0 32768
#define OFF_B1 49152
#define OFF_RACC 65536            // 6*128 floats
#define OFF_CACC (65536 + 3072)   // 6*128 floats
#define SMEM2 (65536 + 6144)

// ---------------- Global scratch ----------------
__device__ __nv_bfloat16 g_fn[(size_t)NN * DD];
__device__ float g_neg[NN], g_pos[NN], g_t1[NN], g_t2[NN], g_t3[NN], g_t4[NN];
__device__ float g_pr[NN];

// ---------------- Helpers ----------------
__device__ __forceinline__ uint32_t smem_u32(const void* p) {
    uint32_t a;
    asm("{ .reg .u64 t; cvta.to.shared.u64 t, %1; cvt.u32.u64 %0, t; }" : "=r"(a) : "l"(p));
    return a;
}
#define SWZ128(o) ((o) ^ (((o) >> 3) & 0x70))

__device__ __forceinline__ void cp16(uint32_t s, const void* g) {
    asm volatile("cp.async.cg.shared.global [%0], [%1], 16;"
                 :: "r"(s), "l"((uint64_t)__cvta_generic_to_global(g)));
}
#define CP_COMMIT() asm volatile("cp.async.commit_group;" ::: "memory")
#define CP_WAIT(n)  asm volatile("cp.async.wait_group %0;" :: "n"(n) : "memory")

__device__ __forceinline__ void ldsm_x4(uint32_t* r, uint32_t addr) {
    asm volatile("ldmatrix.sync.aligned.m8n8.x4.shared.b16 {%0,%1,%2,%3}, [%4];"
                 : "=r"(r[0]), "=r"(r[1]), "=r"(r[2]), "=r"(r[3]) : "r"(addr));
}
__device__ __forceinline__ void mma16816(float* c, const uint32_t* a, uint32_t b0, uint32_t b1) {
    asm volatile("mma.sync.aligned.m16n8k16.row.col.f32.bf16.bf16.f32 "
                 "{%0,%1,%2,%3}, {%4,%5,%6,%7}, {%8,%9}, {%0,%1,%2,%3};"
                 : "+f"(c[0]), "+f"(c[1]), "+f"(c[2]), "+f"(c[3])
                 : "r"(a[0]), "r"(a[1]), "r"(a[2]), "r"(a[3]), "r"(b0), "r"(b1));
}

__device__ __forceinline__ float warp_sum(float v) {
    #pragma unroll
    for (int o = 16; o; o >>= 1) v += __shfl_xor_sync(0xFFFFFFFFu, v, o);
    return v;
}
__device__ __forceinline__ float block_sum(float v, float* red) {
    v = warp_sum(v);
    int w = threadIdx.x >> 5, l = threadIdx.x & 31;
    if (l == 0) red[w] = v;
    __syncthreads();
    int nw = blockDim.x >> 5;
    v = (threadIdx.x < (unsigned)nw) ? red[threadIdx.x] : 0.0f;
    if (w == 0) v = warp_sum(v);
    if (threadIdx.x == 0) red[0] = v;
    __syncthreads();
    return red[0];
}

// ---------------- K0: zero accumulators ----------------
__global__ void k0_zero() {
    int i = blockIdx.x * blockDim.x + threadIdx.x;
    if (i < NN) {
        g_neg[i] = 0.f; g_pos[i] = 0.f; g_t1[i] = 0.f;
        g_t2[i] = 0.f; g_t3[i] = 0.f; g_t4[i] = 0.f;
    }
}

// ---------------- K1: normalize -> bf16 ----------------
__global__ __launch_bounds__(256) void k1_norm(const float* __restrict__ f) {
    __shared__ float red[32];
    int i = blockIdx.x;
    const float* row = f + (size_t)i * DD;
    float v[3], ss = 0.0f;
    #pragma unroll
    for (int k = 0; k < 3; k++) { v[k] = row[threadIdx.x + k * 256]; ss += v[k] * v[k]; }
    float tot = block_sum(ss, red);
    float inv = 1.0f / fmaxf(sqrtf(tot), EPS_NORM);
    __nv_bfloat16* o = g_fn + (size_t)i * DD;
    #pragma unroll
    for (int k = 0; k < 3; k++) o[threadIdx.x + k * 256] = __float2bfloat16(v[k] * inv);
}

// ---------------- K2: mma.sync GEMM (triangle via rectangle map) + dual epilogue ----------------
__device__ __forceinline__ void load_tiles(uint32_t sA, uint32_t sB,
                                           const __nv_bfloat16* A0, const __nv_bfloat16* B0,
                                           int kc, int tid) {
    #pragma unroll
    for (int q = 0; q < 4; q++) {
        int idx = tid + q * 256;
        int r = idx >> 3, seg = idx & 7;              // 128 rows x 8 x 16B
        uint32_t so = SWZ128((uint32_t)(r * 128 + seg * 16));
        cp16(sA + so, A0 + (size_t)r * DD + kc * KC + seg * 8);
        cp16(sB + so, B0 + (size_t)r * DD + kc * KC + seg * 8);
    }
}

__global__ __launch_bounds__(256) void k2_gemm(const float* __restrict__ pm,
                                               const float* __restrict__ nm) {
    // rectangle (65 x 32) -> upper triangle (it <= jt), bijective
    int x = blockIdx.x, y = blockIdx.y;
    int it = y, jt = y + x;
    if (jt >= NT) { it = NT - 1 - y; jt = x - 1; }
    bool diag = (it == jt);

    extern __shared__ char smem[];
    uint32_t sb = smem_u32(smem);
    int tid = threadIdx.x, l = tid & 31, wid = tid >> 5;
    int wm = wid & 3, wn = wid >> 2;     // 4x2 warp grid; warp tile 32x64

    float* racc = (float*)(smem + OFF_RACC);
    float* cacc = (float*)(smem + OFF_CACC);
    for (int z = tid; z < 1536; z += 256) racc[z] = 0.f;   // racc+cacc contiguous

    const __nv_bfloat16* A0 = g_fn + (size_t)it * TILE * DD;
    const __nv_bfloat16* B0 = g_fn + (size_t)jt * TILE * DD;

    float acc[2][8][4];
    #pragma unroll
    for (int m = 0; m < 2; m++)
        #pragma unroll
        for (int n = 0; n < 8; n++)
            #pragma unroll
            for (int xx = 0; xx < 4; xx++) acc[m][n][xx] = 0.f;

    load_tiles(sb + OFF_A0, sb + OFF_B0, A0, B0, 0, tid);
    CP_COMMIT();

    uint32_t aRow = (uint32_t)((wm * 32 + (l & 15)) * 128);
    uint32_t aK   = (uint32_t)((l >> 4) * 16);
    uint32_t bRow = (uint32_t)((wn * 64 + (l & 7) + ((l >> 4) << 3)) * 128);
    uint32_t bK   = (uint32_t)(((l >> 3) & 1) * 16);

    for (int kc = 0; kc < NKC; kc++) {
        if (kc + 1 < NKC) {
            load_tiles(sb + ((kc + 1) & 1 ? OFF_A1 : OFF_A0),
                       sb + ((kc + 1) & 1 ? OFF_B1 : OFF_B0), A0, B0, kc + 1, tid);
            CP_COMMIT();
            CP_WAIT(1);
        } else {
            CP_WAIT(0);
        }
        __syncthreads();
        uint32_t sA = sb + ((kc & 1) ? OFF_A1 : OFF_A0);
        uint32_t sB = sb + ((kc & 1) ? OFF_B1 : OFF_B0);
        #pragma unroll
        for (int ks = 0; ks < 4; ks++) {
            uint32_t a[2][4], b[4][4];
            #pragma unroll
            for (int mf = 0; mf < 2; mf++)
                ldsm_x4(a[mf], sA + (SWZ128(aRow + (uint32_t)(mf * 16 * 128)) ^ (aK + ks * 32)));
            #pragma unroll
            for (int p2 = 0; p2 < 4; p2++)
                ldsm_x4(b[p2], sB + (SWZ128(bRow + (uint32_t)(p2 * 16 * 128)) ^ (bK + ks * 32)));
            #pragma unroll
            for (int mf = 0; mf < 2; mf++)
                #pragma unroll
                for (int nf = 0; nf < 8; nf++)
                    mma16816(acc[mf][nf], a[mf], b[nf >> 1][(nf & 1) * 2], b[nf >> 1][(nf & 1) * 2 + 1]);
        }
        __syncthreads();
    }

    // ---- epilogue: masks + exp; 6 moments, both orientations ----
    int ibase = it * TILE, jbase = jt * TILE;
    int qrow = l >> 2, qcol = (l & 3) * 2;
    float rl[4][6];
    #pragma unroll
    for (int i2 = 0; i2 < 4; i2++)
        #pragma unroll
        for (int v = 0; v < 6; v++) rl[i2][v] = 0.f;

    #pragma unroll
    for (int nf = 0; nf < 8; nf++) {
        float cl[2][6];
        #pragma unroll
        for (int e = 0; e < 2; e++)
            #pragma unroll
            for (int v = 0; v < 6; v++) cl[e][v] = 0.f;

        #pragma unroll
        for (int mf = 0; mf < 2; mf++) {
            #pragma unroll
            for (int h = 0; h < 2; h++) {
                int r = wm * 32 + mf * 16 + qrow + h * 8;
                int i = ibase + r;
                int cb = wn * 64 + nf * 8 + qcol;
                int j0 = jbase + cb;
                float2 pv = *(const float2*)(pm + (size_t)i * NN + j0);
                float2 nv = *(const float2*)(nm + (size_t)i * NN + j0);
                #pragma unroll
                for (int e = 0; e < 2; e++) {
                    float p = e ? pv.y : pv.x;
                    float n = e ? nv.y : nv.x;
                    int ccol = cb + e;
                    if (diag && r == ccol) { p = 0.f; n = 0.f; }
                    float s = acc[mf][nf][h * 2 + e];
                    float ep = __expf(INV_T * s);
                    float y = __fdividef(1.0f, ep);
                    float* R = rl[mf * 2 + h];
                    R[0] += n * ep; R[1] += p; R[2] += p * s;
                    float py = p * y; R[3] += py; py *= y; R[4] += py; py *= y; R[5] += py;
                    if (!diag) {
                        size_t gj = (size_t)(jbase + ccol) * NN + i;
                        float pT = pm[gj], nT = nm[gj];
                        float* C = cl[e];
                        C[0] += nT * ep; C[1] += pT; C[2] += pT * s;
                        float pTy = pT * y; C[3] += pTy; pTy *= y; C[4] += pTy; pTy *= y; C[5] += pTy;
                    }
                }
            }
        }
        if (!diag) {
            #pragma unroll
            for (int e = 0; e < 2; e++) {
                int ccol = wn * 64 + nf * 8 + qcol + e;
                #pragma unroll
                for (int v = 0; v < 6; v++) {
                    float val = cl[e][v];
                    val += __shfl_xor_sync(0xFFFFFFFFu, val, 4);
                    val += __shfl_xor_sync(0xFFFFFFFFu, val, 8);
                    val += __shfl_xor_sync(0xFFFFFFFFu, val, 16);
                    if (l < 4) atomicAdd(&cacc[v * 128 + ccol], val);
                }
            }
        }
    }
    #pragma unroll
    for (int i2 = 0; i2 < 4; i2++) {
        int r = wm * 32 + (i2 >> 1) * 16 + qrow + (i2 & 1) * 8;
        #pragma unroll
        for (int v = 0; v < 6; v++) {
            float val = rl[i2][v];
            val += __shfl_xor_sync(0xFFFFFFFFu, val, 1);
            val += __shfl_xor_sync(0xFFFFFFFFu, val, 2);
            if ((l & 3) == 0) atomicAdd(&racc[v * 128 + r], val);
        }
    }
    __syncthreads();
    if (tid < 128) {
        atomicAdd(&g_neg[ibase + tid], racc[tid]);
        atomicAdd(&g_pos[ibase + tid], racc[128 + tid]);
        atomicAdd(&g_t1[ibase + tid],  racc[256 + tid]);
        atomicAdd(&g_t2[ibase + tid],  racc[384 + tid]);
        atomicAdd(&g_t3[ibase + tid],  racc[512 + tid]);
        atomicAdd(&g_t4[ibase + tid],  racc[640 + tid]);
        if (!diag) {
            atomicAdd(&g_neg[jbase + tid], cacc[tid]);
            atomicAdd(&g_pos[jbase + tid], cacc[128 + tid]);
            atomicAdd(&g_t1[jbase + tid],  cacc[256 + tid]);
            atomicAdd(&g_t2[jbase + tid],  cacc[384 + tid]);
            atomicAdd(&g_t3[jbase + tid],  cacc[512 + tid]);
            atomicAdd(&g_t4[jbase + tid],  cacc[640 + tid]);
        }
    }
}

// ---------------- K4a: per-row loss ----------------
__global__ __launch_bounds__(256) void k4a_row() {
    int i = blockIdx.x * blockDim.x + threadIdx.x;
    if (i >= NN) return;
    float neg = g_neg[i], pos = g_pos[i];
    float c = EPS_LOG * neg;
    float corr = c * g_t2[i] - 0.5f * c * c * g_t3[i] + (c * c * c * (1.0f / 3.0f)) * g_t4[i];
    float num = pos * logf(neg) - INV_T * g_t1[i] - corr;
    g_pr[i] = num / (pos > 0.0f ? pos : 1.0f);
}

// ---------------- K4b: final mean ----------------
__global__ __launch_bounds__(1024) void k4b_final(float* __restrict__ out) {
    __shared__ float red[32];
    float sum = 0.0f;
    #pragma unroll
    for (int k = 0; k < NN / 1024; k++) sum += g_pr[threadIdx.x + k * 1024];
    float tot = block_sum(sum, red);
    if (threadIdx.x == 0) out[0] = tot / (float)NN;
}

// ---------------- launch ----------------
extern "C" void kernel_launch(void* const* d_in, const int* in_sizes, int n_in,
                              void* d_out, int out_size) {
    const float* features = (const float*)d_in[0];
    const float* pmask    = (const float*)d_in[1];
    const float* nmask    = (const float*)d_in[2];
    float* out = (float*)d_out;

    cudaFuncSetAttribute(k2_gemm, cudaFuncAttributeMaxDynamicSharedMemorySize, SMEM2);

    k0_zero<<<(NN + 1023) / 1024, 1024>>>();
    k1_norm<<<NN, 256>>>(features);
    dim3 grid(NT + 1, NT / 2);   // 65 x 32 = 2080 CTAs -> triangle
    k2_gemm<<<grid, 256, SMEM2>>>(pmask, nmask);
    k4a_row<<<NN / 256, 256>>>();
    k4b_final<<<1, 1024>>>(out);
}

// round 11
// speedup vs baseline: 1.5349x; 1.5031x over previous
#include <cuda_runtime.h>
#include <cuda_bf16.h>
#include <cstdint>

// ---------------- Problem constants ----------------
#define NN 8192
#define DD 768
#define TILE 128
#define KC 64                // bf16 k-elems per smem stage (128B rows)
#define NKC (DD / KC)        // 12
#define NT (NN / TILE)       // 64
#define INV_T 10.0f
#define EPS_LOG 1e-6f
#define EPS_NORM 1e-8f

// ---------------- SMEM layout (bytes): 2 stages of (A 16K + B 16K) ----------------
#define OFF_A0 0
#define OFF_A1 16384
#define OFF_B0 32768
#define OFF_B1 49152
#define OFF_RACC 65536            // 6*128 floats
#define OFF_CACC (65536 + 3072)   // 6*128 floats
#define SMEM2 (65536 + 6144)

// ---------------- Global scratch ----------------
__device__ __nv_bfloat16 g_fn[(size_t)NN * DD];
__device__ float g_neg[NN], g_pos[NN], g_t1[NN], g_t2[NN], g_t3[NN], g_t4[NN];
__device__ float g_pr[NN];

// ---------------- Helpers ----------------
__device__ __forceinline__ uint32_t smem_u32(const void* p) {
    uint32_t a;
    asm("{ .reg .u64 t; cvta.to.shared.u64 t, %1; cvt.u32.u64 %0, t; }" : "=r"(a) : "l"(p));
    return a;
}
#define SWZ128(o) ((o) ^ (((o) >> 3) & 0x70))

__device__ __forceinline__ void cp16(uint32_t s, const void* g) {
    asm volatile("cp.async.cg.shared.global [%0], [%1], 16;"
                 :: "r"(s), "l"((uint64_t)__cvta_generic_to_global(g)));
}
#define CP_COMMIT() asm volatile("cp.async.commit_group;" ::: "memory")
#define CP_WAIT(n)  asm volatile("cp.async.wait_group %0;" :: "n"(n) : "memory")

__device__ __forceinline__ void ldsm_x4(uint32_t* r, uint32_t addr) {
    asm volatile("ldmatrix.sync.aligned.m8n8.x4.shared.b16 {%0,%1,%2,%3}, [%4];"
                 : "=r"(r[0]), "=r"(r[1]), "=r"(r[2]), "=r"(r[3]) : "r"(addr));
}
__device__ __forceinline__ void mma16816(float* c, const uint32_t* a, uint32_t b0, uint32_t b1) {
    asm volatile("mma.sync.aligned.m16n8k16.row.col.f32.bf16.bf16.f32 "
                 "{%0,%1,%2,%3}, {%4,%5,%6,%7}, {%8,%9}, {%0,%1,%2,%3};"
                 : "+f"(c[0]), "+f"(c[1]), "+f"(c[2]), "+f"(c[3])
                 : "r"(a[0]), "r"(a[1]), "r"(a[2]), "r"(a[3]), "r"(b0), "r"(b1));
}

__device__ __forceinline__ float warp_sum(float v) {
    #pragma unroll
    for (int o = 16; o; o >>= 1) v += __shfl_xor_sync(0xFFFFFFFFu, v, o);
    return v;
}
__device__ __forceinline__ float block_sum(float v, float* red) {
    v = warp_sum(v);
    int w = threadIdx.x >> 5, l = threadIdx.x & 31;
    if (l == 0) red[w] = v;
    __syncthreads();
    int nw = blockDim.x >> 5;
    v = (threadIdx.x < (unsigned)nw) ? red[threadIdx.x] : 0.0f;
    if (w == 0) v = warp_sum(v);
    if (threadIdx.x == 0) red[0] = v;
    __syncthreads();
    return red[0];
}

// ---------------- K1: normalize -> bf16 (+ zero accumulators) ----------------
__global__ __launch_bounds__(256) void k1_norm(const float* __restrict__ f) {
    __shared__ float red[32];
    int i = blockIdx.x;
    if (threadIdx.x == 0) {
        g_neg[i] = 0.f; g_pos[i] = 0.f; g_t1[i] = 0.f;
        g_t2[i] = 0.f; g_t3[i] = 0.f; g_t4[i] = 0.f;
    }
    const float* row = f + (size_t)i * DD;
    float v[3], ss = 0.0f;
    #pragma unroll
    for (int k = 0; k < 3; k++) { v[k] = row[threadIdx.x + k * 256]; ss += v[k] * v[k]; }
    float tot = block_sum(ss, red);
    float inv = 1.0f / fmaxf(sqrtf(tot), EPS_NORM);
    __nv_bfloat16* o = g_fn + (size_t)i * DD;
    #pragma unroll
    for (int k = 0; k < 3; k++) o[threadIdx.x + k * 256] = __float2bfloat16(v[k] * inv);
}

// ---------------- K2: mma.sync GEMM (upper triangle) + dual-orientation epilogue ----------------
__device__ __forceinline__ void load_tiles(uint32_t sA, uint32_t sB,
                                           const __nv_bfloat16* A0, const __nv_bfloat16* B0,
                                           int kc, int tid) {
    #pragma unroll
    for (int q = 0; q < 4; q++) {
        int idx = tid + q * 256;
        int r = idx >> 3, seg = idx & 7;              // 128 rows x 8 x 16B
        uint32_t so = SWZ128((uint32_t)(r * 128 + seg * 16));
        cp16(sA + so, A0 + (size_t)r * DD + kc * KC + seg * 8);
        cp16(sB + so, B0 + (size_t)r * DD + kc * KC + seg * 8);
    }
}

__global__ __launch_bounds__(256) void k2_gemm(const float* __restrict__ pm,
                                               const float* __restrict__ nm) {
    int it = blockIdx.y, jt = blockIdx.x;
    if (jt < it) return;                 // symmetric: upper triangle only
    bool diag = (it == jt);

    extern __shared__ char smem[];
    uint32_t sb = smem_u32(smem);
    int tid = threadIdx.x, l = tid & 31, wid = tid >> 5;
    int wm = wid & 3, wn = wid >> 2;     // 4x2 warp grid; warp tile 32x64

    float* racc = (float*)(smem + OFF_RACC);
    float* cacc = (float*)(smem + OFF_CACC);
    for (int t = tid; t < 1536; t += 256) racc[t] = 0.f;   // zeros racc+cacc (contiguous)

    const __nv_bfloat16* A0 = g_fn + (size_t)it * TILE * DD;
    const __nv_bfloat16* B0 = g_fn + (size_t)jt * TILE * DD;

    float acc[2][8][4];
    #pragma unroll
    for (int m = 0; m < 2; m++)
        #pragma unroll
        for (int n = 0; n < 8; n++)
            #pragma unroll
            for (int x = 0; x < 4; x++) acc[m][n][x] = 0.f;

    load_tiles(sb + OFF_A0, sb + OFF_B0, A0, B0, 0, tid);
    CP_COMMIT();

    uint32_t aRow = (uint32_t)((wm * 32 + (l & 15)) * 128);
    uint32_t aK   = (uint32_t)((l >> 4) * 16);
    uint32_t bRow = (uint32_t)((wn * 64 + (l & 7) + ((l >> 4) << 3)) * 128);
    uint32_t bK   = (uint32_t)(((l >> 3) & 1) * 16);

    for (int kc = 0; kc < NKC; kc++) {
        if (kc + 1 < NKC) {
            load_tiles(sb + ((kc + 1) & 1 ? OFF_A1 : OFF_A0),
                       sb + ((kc + 1) & 1 ? OFF_B1 : OFF_B0), A0, B0, kc + 1, tid);
            CP_COMMIT();
            CP_WAIT(1);
        } else {
            CP_WAIT(0);
        }
        __syncthreads();
        uint32_t sA = sb + ((kc & 1) ? OFF_A1 : OFF_A0);
        uint32_t sB = sb + ((kc & 1) ? OFF_B1 : OFF_B0);
        #pragma unroll
        for (int ks = 0; ks < 4; ks++) {
            uint32_t a[2][4], b[4][4];
            #pragma unroll
            for (int mf = 0; mf < 2; mf++)
                ldsm_x4(a[mf], sA + (SWZ128(aRow + (uint32_t)(mf * 16 * 128)) ^ (aK + ks * 32)));
            #pragma unroll
            for (int p2 = 0; p2 < 4; p2++)
                ldsm_x4(b[p2], sB + (SWZ128(bRow + (uint32_t)(p2 * 16 * 128)) ^ (bK + ks * 32)));
            #pragma unroll
            for (int mf = 0; mf < 2; mf++)
                #pragma unroll
                for (int nf = 0; nf < 8; nf++)
                    mma16816(acc[mf][nf], a[mf], b[nf >> 1][(nf & 1) * 2], b[nf >> 1][(nf & 1) * 2 + 1]);
        }
        __syncthreads();
    }

    // ---- epilogue: masks + exp; 6 moments, both orientations ----
    int ibase = it * TILE, jbase = jt * TILE;
    int qrow = l >> 2, qcol = (l & 3) * 2;
    float rl[4][6];
    #pragma unroll
    for (int i2 = 0; i2 < 4; i2++)
        #pragma unroll
        for (int v = 0; v < 6; v++) rl[i2][v] = 0.f;

    #pragma unroll
    for (int nf = 0; nf < 8; nf++) {
        float cl[2][6];
        #pragma unroll
        for (int e = 0; e < 2; e++)
            #pragma unroll
            for (int v = 0; v < 6; v++) cl[e][v] = 0.f;

        #pragma unroll
        for (int mf = 0; mf < 2; mf++) {
            #pragma unroll
            for (int h = 0; h < 2; h++) {
                int r = wm * 32 + mf * 16 + qrow + h * 8;
                int i = ibase + r;
                int cb = wn * 64 + nf * 8 + qcol;
                int j0 = jbase + cb;
                float2 pv = *(const float2*)(pm + (size_t)i * NN + j0);
                float2 nv = *(const float2*)(nm + (size_t)i * NN + j0);
                #pragma unroll
                for (int e = 0; e < 2; e++) {
                    float p = e ? pv.y : pv.x;
                    float n = e ? nv.y : nv.x;
                    int ccol = cb + e;
                    if (diag && r == ccol) { p = 0.f; n = 0.f; }
                    float s = acc[mf][nf][h * 2 + e];
                    float ep = __expf(INV_T * s);
                    float y = __fdividef(1.0f, ep);
                    float* R = rl[mf * 2 + h];
                    R[0] += n * ep; R[1] += p; R[2] += p * s;
                    float py = p * y; R[3] += py; py *= y; R[4] += py; py *= y; R[5] += py;
                    if (!diag) {
                        size_t gj = (size_t)(jbase + ccol) * NN + i;
                        float pT = pm[gj], nT = nm[gj];
                        float* C = cl[e];
                        C[0] += nT * ep; C[1] += pT; C[2] += pT * s;
                        float pTy = pT * y; C[3] += pTy; pTy *= y; C[4] += pTy; pTy *= y; C[5] += pTy;
                    }
                }
            }
        }
        if (!diag) {
            #pragma unroll
            for (int e = 0; e < 2; e++) {
                int ccol = wn * 64 + nf * 8 + qcol + e;
                #pragma unroll
                for (int v = 0; v < 6; v++) {
                    float val = cl[e][v];
                    val += __shfl_xor_sync(0xFFFFFFFFu, val, 4);
                    val += __shfl_xor_sync(0xFFFFFFFFu, val, 8);
                    val += __shfl_xor_sync(0xFFFFFFFFu, val, 16);
                    if (l < 4) atomicAdd(&cacc[v * 128 + ccol], val);
                }
            }
        }
    }
    #pragma unroll
    for (int i2 = 0; i2 < 4; i2++) {
        int r = wm * 32 + (i2 >> 1) * 16 + qrow + (i2 & 1) * 8;
        #pragma unroll
        for (int v = 0; v < 6; v++) {
            float val = rl[i2][v];
            val += __shfl_xor_sync(0xFFFFFFFFu, val, 1);
            val += __shfl_xor_sync(0xFFFFFFFFu, val, 2);
            if ((l & 3) == 0) atomicAdd(&racc[v * 128 + r], val);
        }
    }
    __syncthreads();
    if (tid < 128) {
        atomicAdd(&g_neg[ibase + tid], racc[tid]);
        atomicAdd(&g_pos[ibase + tid], racc[128 + tid]);
        atomicAdd(&g_t1[ibase + tid],  racc[256 + tid]);
        atomicAdd(&g_t2[ibase + tid],  racc[384 + tid]);
        atomicAdd(&g_t3[ibase + tid],  racc[512 + tid]);
        atomicAdd(&g_t4[ibase + tid],  racc[640 + tid]);
        if (!diag) {
            atomicAdd(&g_neg[jbase + tid], cacc[tid]);
            atomicAdd(&g_pos[jbase + tid], cacc[128 + tid]);
            atomicAdd(&g_t1[jbase + tid],  cacc[256 + tid]);
            atomicAdd(&g_t2[jbase + tid],  cacc[384 + tid]);
            atomicAdd(&g_t3[jbase + tid],  cacc[512 + tid]);
            atomicAdd(&g_t4[jbase + tid],  cacc[640 + tid]);
        }
    }
}

// ---------------- K4a: per-row loss ----------------
__global__ __launch_bounds__(256) void k4a_row() {
    int i = blockIdx.x * blockDim.x + threadIdx.x;
    if (i >= NN) return;
    float neg = g_neg[i], pos = g_pos[i];
    float c = EPS_LOG * neg;
    float corr = c * g_t2[i] - 0.5f * c * c * g_t3[i] + (c * c * c * (1.0f / 3.0f)) * g_t4[i];
    float num = pos * logf(neg) - INV_T * g_t1[i] - corr;
    g_pr[i] = num / (pos > 0.0f ? pos : 1.0f);
}

// ---------------- K4b: final mean ----------------
__global__ __launch_bounds__(1024) void k4b_final(float* __restrict__ out) {
    __shared__ float red[32];
    float sum = 0.0f;
    #pragma unroll
    for (int k = 0; k < NN / 1024; k++) sum += g_pr[threadIdx.x + k * 1024];
    float tot = block_sum(sum, red);
    if (threadIdx.x == 0) out[0] = tot / (float)NN;
}

// ---------------- launch: 4 kernels/call so ncu (-s 5 -c 1) captures k2 ----------------
extern "C" void kernel_launch(void* const* d_in, const int* in_sizes, int n_in,
                              void* d_out, int out_size) {
    const float* features = (const float*)d_in[0];
    const float* pmask    = (const float*)d_in[1];
    const float* nmask    = (const float*)d_in[2];
    float* out = (float*)d_out;

    cudaFuncSetAttribute(k2_gemm, cudaFuncAttributeMaxDynamicSharedMemorySize, SMEM2);

    k1_norm<<<NN, 256>>>(features);           // launch 1 (mod 4)
    dim3 grid(NT, NT);
    k2_gemm<<<grid, 256, SMEM2>>>(pmask, nmask);  // launch 2 (mod 4) -> ncu lands here
    k4a_row<<<NN / 256, 256>>>();             // launch 3
    k4b_final<<<1, 1024>>>(out);              // launch 4
}